// round 2
// baseline (speedup 1.0000x reference)
#include <cuda_runtime.h>
#include <math.h>

// Problem constants (B=4, L=2048, H=8, E=64)
#define BB 4
#define LL 2048
#define HH 8
#define EE 64
#define NBH (BB*HH)           // 32
#define NROWS (NBH*LL)        // 65536
#define SCALEF 0.125f         // 1/sqrt(64)
#define STRIDE_L (HH*EE)      // 512 floats between consecutive l in [B,L,H,E]

// Scratch (device globals — no allocation allowed)
__device__ float g_rowsum[NROWS];
__device__ float g_sigv[NROWS];
__device__ float g_coef[NROWS];
__device__ float g_inv2s2[NROWS];

// ---------------------------------------------------------------------------
// K0: per-row sigma transform.
// sig = 3^(sigmoid(5x)+1e-5) - 1, computed to match fp32 reference rounding:
// pow done in double, rounded to f32, then the cancellation-prone "-1" in f32.
// ---------------------------------------------------------------------------
__global__ void k_sig(const float* __restrict__ sigma) {
    int i = blockIdx.x * 256 + threadIdx.x;
    if (i >= NROWS) return;
    int bh = i >> 11;          // /2048
    int l  = i & 2047;
    int b = bh >> 3, h = bh & 7;
    float x = sigma[((size_t)b * LL + l) * HH + h];
    float s32 = (float)(1.0 / (1.0 + exp(-5.0 * (double)x)));
    float sg  = s32 + 1e-5f;
    float p   = (float)exp((double)sg * 1.0986122886681098);  // 3^sg rounded to f32
    float s   = p - 1.0f;
    g_sigv[i]   = s;
    g_coef[i]   = 1.0f / (2.5066282746310002f * s);  // 1/(sqrt(2pi)*s)
    g_inv2s2[i] = 1.0f / (2.0f * s * s);
}

// ---------------------------------------------------------------------------
// K1: causal softmax denominators.  rowsum[b,h,l] = sum_{j<=l} exp(scale*q.k_j)
// Tiled 128x128 fp32 GEMM, 16x16 threads, 8x8 microtile, E chunked by 32.
// ---------------------------------------------------------------------------
__global__ void __launch_bounds__(256) k_rowsum(const float* __restrict__ Q,
                                                const float* __restrict__ K) {
    __shared__ float Qs[32][132];
    __shared__ float Ks[32][132];
    __shared__ float srow[128];
    int bh = blockIdx.y, b = bh >> 3, h = bh & 7;
    int ti = blockIdx.x, l0 = ti * 128;
    int tid = threadIdx.x, tx = tid & 15, ty = tid >> 4;
    if (tid < 128) srow[tid] = 0.f;

    const float* Qb = Q + ((size_t)b * LL) * STRIDE_L + (size_t)h * EE;
    const float* Kb = K + ((size_t)b * LL) * STRIDE_L + (size_t)h * EE;

    float lsum[8];
#pragma unroll
    for (int r = 0; r < 8; r++) lsum[r] = 0.f;

    for (int tj = 0; tj <= ti; tj++) {
        int j0 = tj * 128;
        float acc[8][8];
#pragma unroll
        for (int r = 0; r < 8; r++)
#pragma unroll
            for (int c = 0; c < 8; c++) acc[r][c] = 0.f;

        for (int ec = 0; ec < 2; ec++) {
            __syncthreads();
            {
                int e = tid & 31, lr = tid >> 5;
#pragma unroll
                for (int it = 0; it < 16; it++) {
                    int l = lr + it * 8;
                    Qs[e][l] = Qb[(size_t)(l0 + l) * STRIDE_L + ec * 32 + e];
                    Ks[e][l] = Kb[(size_t)(j0 + l) * STRIDE_L + ec * 32 + e];
                }
            }
            __syncthreads();
#pragma unroll
            for (int kk = 0; kk < 32; kk++) {
                float a[8], bv[8];
                *(float4*)&a[0]  = *(const float4*)&Qs[kk][ty * 8];
                *(float4*)&a[4]  = *(const float4*)&Qs[kk][ty * 8 + 4];
                *(float4*)&bv[0] = *(const float4*)&Ks[kk][tx * 8];
                *(float4*)&bv[4] = *(const float4*)&Ks[kk][tx * 8 + 4];
#pragma unroll
                for (int r = 0; r < 8; r++)
#pragma unroll
                    for (int c = 0; c < 8; c++) acc[r][c] += a[r] * bv[c];
            }
        }
        if (tj < ti) {
#pragma unroll
            for (int r = 0; r < 8; r++) {
                float s = 0.f;
#pragma unroll
                for (int c = 0; c < 8; c++) s += __expf(SCALEF * acc[r][c]);
                lsum[r] += s;
            }
        } else {  // diagonal tile: mask j > l
#pragma unroll
            for (int r = 0; r < 8; r++) {
                int lr_ = ty * 8 + r;
#pragma unroll
                for (int c = 0; c < 8; c++) {
                    int jr_ = tx * 8 + c;
                    if (jr_ <= lr_) lsum[r] += __expf(SCALEF * acc[r][c]);
                }
            }
        }
    }
    __syncthreads();
#pragma unroll
    for (int r = 0; r < 8; r++) atomicAdd(&srow[ty * 8 + r], lsum[r]);
    __syncthreads();
    if (tid < 128) g_rowsum[(size_t)bh * LL + l0 + tid] = srow[tid];
}

// ---------------------------------------------------------------------------
// K2: recompute scores, write normalized series (causal tiles incl. diagonal).
// ---------------------------------------------------------------------------
__global__ void __launch_bounds__(256) k_series(const float* __restrict__ Q,
                                                const float* __restrict__ K,
                                                float* __restrict__ series) {
    __shared__ float Qs[32][132];
    __shared__ float Ks[32][132];
    int bh = blockIdx.y, b = bh >> 3, h = bh & 7;
    int ti = blockIdx.x, l0 = ti * 128;
    int tid = threadIdx.x, tx = tid & 15, ty = tid >> 4;

    const float* Qb = Q + ((size_t)b * LL) * STRIDE_L + (size_t)h * EE;
    const float* Kb = K + ((size_t)b * LL) * STRIDE_L + (size_t)h * EE;

    float invl[8];
#pragma unroll
    for (int r = 0; r < 8; r++)
        invl[r] = 1.0f / g_rowsum[(size_t)bh * LL + l0 + ty * 8 + r];

    for (int tj = 0; tj <= ti; tj++) {
        int j0 = tj * 128;
        float acc[8][8];
#pragma unroll
        for (int r = 0; r < 8; r++)
#pragma unroll
            for (int c = 0; c < 8; c++) acc[r][c] = 0.f;

        for (int ec = 0; ec < 2; ec++) {
            __syncthreads();
            {
                int e = tid & 31, lr = tid >> 5;
#pragma unroll
                for (int it = 0; it < 16; it++) {
                    int l = lr + it * 8;
                    Qs[e][l] = Qb[(size_t)(l0 + l) * STRIDE_L + ec * 32 + e];
                    Ks[e][l] = Kb[(size_t)(j0 + l) * STRIDE_L + ec * 32 + e];
                }
            }
            __syncthreads();
#pragma unroll
            for (int kk = 0; kk < 32; kk++) {
                float a[8], bv[8];
                *(float4*)&a[0]  = *(const float4*)&Qs[kk][ty * 8];
                *(float4*)&a[4]  = *(const float4*)&Qs[kk][ty * 8 + 4];
                *(float4*)&bv[0] = *(const float4*)&Ks[kk][tx * 8];
                *(float4*)&bv[4] = *(const float4*)&Ks[kk][tx * 8 + 4];
#pragma unroll
                for (int r = 0; r < 8; r++)
#pragma unroll
                    for (int c = 0; c < 8; c++) acc[r][c] += a[r] * bv[c];
            }
        }
        // epilogue: p = exp(scale*s)/rowsum, masked; vectorized stores
#pragma unroll
        for (int r = 0; r < 8; r++) {
            int lr_ = ty * 8 + r;
            int gl  = l0 + lr_;
            float p[8];
#pragma unroll
            for (int c = 0; c < 8; c++) {
                int gj = j0 + tx * 8 + c;
                float e = __expf(SCALEF * acc[r][c]) * invl[r];
                p[c] = (gj <= gl) ? e : 0.f;
            }
            float* dst = series + ((size_t)bh * LL + gl) * LL + j0 + tx * 8;
            *(float4*)&dst[0] = make_float4(p[0], p[1], p[2], p[3]);
            *(float4*)&dst[4] = make_float4(p[4], p[5], p[6], p[7]);
        }
    }
}

// ---------------------------------------------------------------------------
// K4: prior + sig for ALL tiles; series=0 for strictly-upper tiles.
// Store-bound elementwise kernel, float4 stores, 512B/warp.
// ---------------------------------------------------------------------------
__global__ void __launch_bounds__(256) k_prior(float* __restrict__ prior,
                                               float* __restrict__ sig,
                                               float* __restrict__ series) {
    int bh = blockIdx.z;
    int ti = blockIdx.y, tj = blockIdx.x;
    int l0 = ti * 128, j0 = tj * 128;
    bool upper = (tj > ti);
    int tid = threadIdx.x;
    int c4 = (tid & 31) * 4;      // column group (float4)
    int r0 = tid >> 5;            // 0..7
#pragma unroll 4
    for (int it = 0; it < 16; it++) {
        int lr = r0 + it * 8;
        int gl = l0 + lr;
        size_t rowi = (size_t)bh * LL + gl;
        float coef = g_coef[rowi];
        float i2s  = g_inv2s2[rowi];
        float sv   = g_sigv[rowi];
        float p[4];
#pragma unroll
        for (int c = 0; c < 4; c++) {
            int gj = j0 + c4 + c;
            int d  = gl - gj;
            float d2 = (float)(d * d);
            p[c] = coef * __expf(-d2 * i2s);
        }
        size_t idx = rowi * LL + j0 + c4;
        *(float4*)&prior[idx] = make_float4(p[0], p[1], p[2], p[3]);
        *(float4*)&sig[idx]   = make_float4(sv, sv, sv, sv);
        if (upper)
            *(float4*)&series[idx] = make_float4(0.f, 0.f, 0.f, 0.f);
    }
}

// ---------------------------------------------------------------------------
// K3: V[b,l,h,e] = sum_s series[b,h,l,s] * values[b,s,h,e]  (causal tiles only)
// ---------------------------------------------------------------------------
__global__ void __launch_bounds__(256) k_pv(const float* __restrict__ series,
                                            const float* __restrict__ V,
                                            float* __restrict__ out) {
    __shared__ float As[32][132];   // [s][l]
    __shared__ float Bs[32][64];    // [s][e]
    int bh = blockIdx.y, b = bh >> 3, h = bh & 7;
    int ti = blockIdx.x, l0 = ti * 128;
    int tid = threadIdx.x, tx = tid & 15, ty = tid >> 4;

    const float* Sb = series + ((size_t)bh * LL + l0) * LL;

    float acc[8][4];
#pragma unroll
    for (int r = 0; r < 8; r++)
#pragma unroll
        for (int c = 0; c < 4; c++) acc[r][c] = 0.f;

    for (int tj = 0; tj <= ti; tj++) {
        for (int sc = 0; sc < 4; sc++) {
            int s0 = tj * 128 + sc * 32;
            __syncthreads();
            {
                int s = tid & 31, lr = tid >> 5;
#pragma unroll
                for (int it = 0; it < 16; it++) {
                    int l = lr + it * 8;
                    As[s][l] = Sb[(size_t)l * LL + s0 + s];
                }
            }
            {
                int e = tid & 63, sr = tid >> 6;
#pragma unroll
                for (int it = 0; it < 8; it++) {
                    int s = sr + it * 4;
                    Bs[s][e] = V[(((size_t)b * LL + s0 + s) * HH + h) * EE + e];
                }
            }
            __syncthreads();
#pragma unroll
            for (int ss = 0; ss < 32; ss++) {
                float a[8], bv[4];
                *(float4*)&a[0]  = *(const float4*)&As[ss][ty * 8];
                *(float4*)&a[4]  = *(const float4*)&As[ss][ty * 8 + 4];
                *(float4*)&bv[0] = *(const float4*)&Bs[ss][tx * 4];
#pragma unroll
                for (int r = 0; r < 8; r++)
#pragma unroll
                    for (int c = 0; c < 4; c++) acc[r][c] += a[r] * bv[c];
            }
        }
    }
#pragma unroll
    for (int r = 0; r < 8; r++) {
        int gl = l0 + ty * 8 + r;
        float* dst = out + (((size_t)b * LL + gl) * HH + h) * EE + tx * 4;
        *(float4*)dst = make_float4(acc[r][0], acc[r][1], acc[r][2], acc[r][3]);
    }
}

// ---------------------------------------------------------------------------
extern "C" void kernel_launch(void* const* d_in, const int* in_sizes, int n_in,
                              void* d_out, int out_size) {
    const float* Q = (const float*)d_in[0];
    const float* K = (const float*)d_in[1];
    const float* V = (const float*)d_in[2];
    const float* S = (const float*)d_in[3];
    float* out = (float*)d_out;

    float* outV      = out;                                   // [B,L,H,E]
    float* outSeries = outV + (size_t)BB * LL * HH * EE;      // [B,H,L,L]
    float* outPrior  = outSeries + (size_t)NBH * LL * LL;     // [B,H,L,L]
    float* outSig    = outPrior + (size_t)NBH * LL * LL;      // [B,H,L,L]

    k_sig<<<NROWS / 256, 256>>>(S);
    k_rowsum<<<dim3(16, NBH), 256>>>(Q, K);
    k_series<<<dim3(16, NBH), 256>>>(Q, K, outSeries);
    k_prior<<<dim3(16, 16, NBH), 256>>>(outPrior, outSig, outSeries);
    k_pv<<<dim3(16, NBH), 256>>>(outSeries, V, outV);
}

// round 3
// speedup vs baseline: 1.2262x; 1.2262x over previous
#include <cuda_runtime.h>
#include <math.h>

// Problem constants (B=4, L=2048, H=8, E=64)
#define BB 4
#define LL 2048
#define HH 8
#define EE 64
#define NBH (BB*HH)           // 32
#define NROWS (NBH*LL)        // 65536
#define SCALEF 0.125f         // 1/sqrt(64)
#define STRIDE_L (HH*EE)      // 512 floats between consecutive l in [B,L,H,E]

// Scratch (device globals — no allocation allowed)
__device__ float g_invsum[NROWS];   // reciprocal of causal softmax row sum
__device__ float g_sigv[NROWS];
__device__ float g_coef[NROWS];
__device__ float g_inv2s2[NROWS];

// ---------------------------------------------------------------------------
// Packed fp32x2 helpers (sm_100+). ptxas never emits FFMA2 from C++; the only
// way to the full 128-lane/cyc fp32 rate on sm_103a is explicit fma.rn.f32x2.
// ---------------------------------------------------------------------------
__device__ __forceinline__ void fma2(unsigned long long& d,
                                     unsigned long long a,
                                     unsigned long long b) {
    asm("fma.rn.f32x2 %0, %1, %2, %0;" : "+l"(d) : "l"(a), "l"(b));
}
__device__ __forceinline__ unsigned long long pack2(float x, float y) {
    unsigned long long r;
    asm("mov.b64 %0, {%1, %2};" : "=l"(r) : "f"(x), "f"(y));
    return r;
}
__device__ __forceinline__ float2 unpack2(unsigned long long v) {
    float2 f;
    asm("mov.b64 {%0, %1}, %2;" : "=f"(f.x), "=f"(f.y) : "l"(v));
    return f;
}

// ---------------------------------------------------------------------------
// K0: per-row sigma transform.
// sig = 3^(sigmoid(5x)+1e-5) - 1, pow in double then rounded to f32 to match
// the reference's fp32 quantization before the cancellation-prone "-1".
// ---------------------------------------------------------------------------
__global__ void k_sig(const float* __restrict__ sigma) {
    int i = blockIdx.x * 256 + threadIdx.x;
    if (i >= NROWS) return;
    int bh = i >> 11;
    int l  = i & 2047;
    int b = bh >> 3, h = bh & 7;
    float x = sigma[((size_t)b * LL + l) * HH + h];
    float s32 = (float)(1.0 / (1.0 + exp(-5.0 * (double)x)));
    float sg  = s32 + 1e-5f;
    float p   = (float)exp((double)sg * 1.0986122886681098);  // 3^sg, f32-rounded
    float s   = p - 1.0f;
    g_sigv[i]   = s;
    g_coef[i]   = 1.0f / (2.5066282746310002f * s);  // 1/(sqrt(2pi)*s)
    g_inv2s2[i] = 1.0f / (2.0f * s * s);
}

// ---------------------------------------------------------------------------
// K1: single causal QK^T pass. Writes UNNORMALIZED exp(scale*q.k) to series
// and accumulates row sums; stores reciprocal row sums to g_invsum.
// 128x128 tiles, 16x16 threads, 8x8 microtile, rows paired for fma.f32x2.
// ---------------------------------------------------------------------------
__global__ void __launch_bounds__(256) k_scores(const float* __restrict__ Q,
                                                const float* __restrict__ K,
                                                float* __restrict__ series) {
    __shared__ float Qs[32][132];
    __shared__ float Ks[32][132];
    __shared__ float srow[128];
    int bh = blockIdx.y, b = bh >> 3, h = bh & 7;
    int ti = 15 - blockIdx.x;          // heavy blocks first
    int l0 = ti * 128;
    int tid = threadIdx.x, tx = tid & 15, ty = tid >> 4;
    if (tid < 128) srow[tid] = 0.f;

    const float* Qb = Q + ((size_t)b * LL) * STRIDE_L + (size_t)h * EE;
    const float* Kb = K + ((size_t)b * LL) * STRIDE_L + (size_t)h * EE;

    float lsum[8];
#pragma unroll
    for (int r = 0; r < 8; r++) lsum[r] = 0.f;

    for (int tj = 0; tj <= ti; tj++) {
        int j0 = tj * 128;
        unsigned long long acc2[4][8];   // [row-pair][col]
#pragma unroll
        for (int r2 = 0; r2 < 4; r2++)
#pragma unroll
            for (int c = 0; c < 8; c++) acc2[r2][c] = 0ull;

        for (int ec = 0; ec < 2; ec++) {
            __syncthreads();
            {
                int e = tid & 31, lr = tid >> 5;
#pragma unroll
                for (int it = 0; it < 16; it++) {
                    int l = lr + it * 8;
                    Qs[e][l] = Qb[(size_t)(l0 + l) * STRIDE_L + ec * 32 + e];
                    Ks[e][l] = Kb[(size_t)(j0 + l) * STRIDE_L + ec * 32 + e];
                }
            }
            __syncthreads();
#pragma unroll
            for (int kk = 0; kk < 32; kk++) {
                ulonglong2 qa = *(const ulonglong2*)&Qs[kk][ty * 8];
                ulonglong2 qb = *(const ulonglong2*)&Qs[kk][ty * 8 + 4];
                unsigned long long a2[4] = {qa.x, qa.y, qb.x, qb.y};
                float4 b0 = *(const float4*)&Ks[kk][tx * 8];
                float4 b1 = *(const float4*)&Ks[kk][tx * 8 + 4];
                float bf[8] = {b0.x, b0.y, b0.z, b0.w, b1.x, b1.y, b1.z, b1.w};
#pragma unroll
                for (int c = 0; c < 8; c++) {
                    unsigned long long bb = pack2(bf[c], bf[c]);
#pragma unroll
                    for (int r2 = 0; r2 < 4; r2++) fma2(acc2[r2][c], a2[r2], bb);
                }
            }
        }
        // epilogue: store unnormalized exp, accumulate row sums
#pragma unroll
        for (int r2 = 0; r2 < 4; r2++) {
            int gl0 = l0 + ty * 8 + 2 * r2;
            int gl1 = gl0 + 1;
            float p0[8], p1[8];
#pragma unroll
            for (int c = 0; c < 8; c++) {
                int gj = j0 + tx * 8 + c;
                float2 v = unpack2(acc2[r2][c]);
                float e0 = __expf(SCALEF * v.x);
                float e1 = __expf(SCALEF * v.y);
                p0[c] = (gj <= gl0) ? e0 : 0.f;
                p1[c] = (gj <= gl1) ? e1 : 0.f;
                lsum[2 * r2]     += p0[c];
                lsum[2 * r2 + 1] += p1[c];
            }
            float* d0 = series + ((size_t)bh * LL + gl0) * LL + j0 + tx * 8;
            float* d1 = series + ((size_t)bh * LL + gl1) * LL + j0 + tx * 8;
            *(float4*)&d0[0] = make_float4(p0[0], p0[1], p0[2], p0[3]);
            *(float4*)&d0[4] = make_float4(p0[4], p0[5], p0[6], p0[7]);
            *(float4*)&d1[0] = make_float4(p1[0], p1[1], p1[2], p1[3]);
            *(float4*)&d1[4] = make_float4(p1[4], p1[5], p1[6], p1[7]);
        }
    }
    __syncthreads();
#pragma unroll
    for (int r = 0; r < 8; r++) atomicAdd(&srow[ty * 8 + r], lsum[r]);
    __syncthreads();
    if (tid < 128) g_invsum[(size_t)bh * LL + l0 + tid] = 1.0f / srow[tid];
}

// ---------------------------------------------------------------------------
// K2: V = (unnormalized series) @ values, rows scaled by invsum at the end.
// Must run BEFORE k_prior normalizes series in place.
// ---------------------------------------------------------------------------
__global__ void __launch_bounds__(256) k_pv(const float* __restrict__ series,
                                            const float* __restrict__ V,
                                            float* __restrict__ out) {
    __shared__ float As[32][132];   // [s][l]
    __shared__ float Bs[32][64];    // [s][e]
    int bh = blockIdx.y, b = bh >> 3, h = bh & 7;
    int ti = 15 - blockIdx.x;
    int l0 = ti * 128;
    int tid = threadIdx.x, tx = tid & 15, ty = tid >> 4;

    const float* Sb = series + ((size_t)bh * LL + l0) * LL;

    unsigned long long acc2[4][4];  // [row-pair][e-col]
#pragma unroll
    for (int r2 = 0; r2 < 4; r2++)
#pragma unroll
        for (int c = 0; c < 4; c++) acc2[r2][c] = 0ull;

    for (int tj = 0; tj <= ti; tj++) {
        for (int sc = 0; sc < 4; sc++) {
            int s0 = tj * 128 + sc * 32;
            __syncthreads();
            {
                int s = tid & 31, lr = tid >> 5;
#pragma unroll
                for (int it = 0; it < 16; it++) {
                    int l = lr + it * 8;
                    As[s][l] = Sb[(size_t)l * LL + s0 + s];
                }
            }
            {
                int e = tid & 63, sr = tid >> 6;
#pragma unroll
                for (int it = 0; it < 8; it++) {
                    int s = sr + it * 4;
                    Bs[s][e] = V[(((size_t)b * LL + s0 + s) * HH + h) * EE + e];
                }
            }
            __syncthreads();
#pragma unroll
            for (int ss = 0; ss < 32; ss++) {
                ulonglong2 aa0 = *(const ulonglong2*)&As[ss][ty * 8];
                ulonglong2 aa1 = *(const ulonglong2*)&As[ss][ty * 8 + 4];
                unsigned long long a2[4] = {aa0.x, aa0.y, aa1.x, aa1.y};
                float4 bv = *(const float4*)&Bs[ss][tx * 4];
                float bf[4] = {bv.x, bv.y, bv.z, bv.w};
#pragma unroll
                for (int c = 0; c < 4; c++) {
                    unsigned long long bb = pack2(bf[c], bf[c]);
#pragma unroll
                    for (int r2 = 0; r2 < 4; r2++) fma2(acc2[r2][c], a2[r2], bb);
                }
            }
        }
    }
#pragma unroll
    for (int r2 = 0; r2 < 4; r2++) {
        int gl0 = l0 + ty * 8 + 2 * r2;
        int gl1 = gl0 + 1;
        float i0 = g_invsum[(size_t)bh * LL + gl0];
        float i1 = g_invsum[(size_t)bh * LL + gl1];
        float p0[4], p1[4];
#pragma unroll
        for (int c = 0; c < 4; c++) {
            float2 v = unpack2(acc2[r2][c]);
            p0[c] = v.x * i0;
            p1[c] = v.y * i1;
        }
        float* d0 = out + (((size_t)b * LL + gl0) * HH + h) * EE + tx * 4;
        float* d1 = out + (((size_t)b * LL + gl1) * HH + h) * EE + tx * 4;
        *(float4*)d0 = make_float4(p0[0], p0[1], p0[2], p0[3]);
        *(float4*)d1 = make_float4(p1[0], p1[1], p1[2], p1[3]);
    }
}

// ---------------------------------------------------------------------------
// K3: prior + sig everywhere; series: zeros in strictly-upper tiles,
// in-place normalization (x *= invsum) in lower+diagonal tiles.
// Store-bound streaming kernel, float4 accesses.
// ---------------------------------------------------------------------------
__global__ void __launch_bounds__(256) k_prior(float* __restrict__ prior,
                                               float* __restrict__ sig,
                                               float* __restrict__ series) {
    int bh = blockIdx.z;
    int ti = blockIdx.y, tj = blockIdx.x;
    int l0 = ti * 128, j0 = tj * 128;
    bool upper = (tj > ti);
    int tid = threadIdx.x;
    int c4 = (tid & 31) * 4;
    int r0 = tid >> 5;
#pragma unroll 4
    for (int it = 0; it < 16; it++) {
        int lr = r0 + it * 8;
        int gl = l0 + lr;
        size_t rowi = (size_t)bh * LL + gl;
        float coef = g_coef[rowi];
        float i2s  = g_inv2s2[rowi];
        float sv   = g_sigv[rowi];
        float p[4];
#pragma unroll
        for (int c = 0; c < 4; c++) {
            int gj = j0 + c4 + c;
            int d  = gl - gj;
            float d2 = (float)(d * d);
            p[c] = coef * __expf(-d2 * i2s);
        }
        size_t idx = rowi * LL + j0 + c4;
        *(float4*)&prior[idx] = make_float4(p[0], p[1], p[2], p[3]);
        *(float4*)&sig[idx]   = make_float4(sv, sv, sv, sv);
        if (upper) {
            *(float4*)&series[idx] = make_float4(0.f, 0.f, 0.f, 0.f);
        } else {
            float inv = g_invsum[rowi];
            float4 s = *(const float4*)&series[idx];
            s.x *= inv; s.y *= inv; s.z *= inv; s.w *= inv;
            *(float4*)&series[idx] = s;
        }
    }
}

// ---------------------------------------------------------------------------
extern "C" void kernel_launch(void* const* d_in, const int* in_sizes, int n_in,
                              void* d_out, int out_size) {
    const float* Q = (const float*)d_in[0];
    const float* K = (const float*)d_in[1];
    const float* V = (const float*)d_in[2];
    const float* S = (const float*)d_in[3];
    float* out = (float*)d_out;

    float* outV      = out;                                   // [B,L,H,E]
    float* outSeries = outV + (size_t)BB * LL * HH * EE;      // [B,H,L,L]
    float* outPrior  = outSeries + (size_t)NBH * LL * LL;     // [B,H,L,L]
    float* outSig    = outPrior + (size_t)NBH * LL * LL;      // [B,H,L,L]

    k_sig<<<NROWS / 256, 256>>>(S);
    k_scores<<<dim3(16, NBH), 256>>>(Q, K, outSeries);   // unnormalized + invsum
    k_pv<<<dim3(16, NBH), 256>>>(outSeries, V, outV);    // reads unnormalized
    k_prior<<<dim3(16, 16, NBH), 256>>>(outPrior, outSig, outSeries);  // normalizes
}

// round 4
// speedup vs baseline: 1.3312x; 1.0856x over previous
#include <cuda_runtime.h>
#include <math.h>

// Problem constants (B=4, L=2048, H=8, E=64)
#define BB 4
#define LL 2048
#define HH 8
#define EE 64
#define NBH (BB*HH)           // 32
#define NROWS (NBH*LL)        // 65536
#define SCALEF 0.125f         // 1/sqrt(64)
#define STRIDE_L (HH*EE)      // 512

// Scratch (device globals — no allocation allowed)
__device__ float g_sigv[NROWS];
__device__ float g_coef[NROWS];
__device__ float g_inv2s2[NROWS];

// Shared-memory layout for the fused kernel (float offsets)
#define OFF_Q  0                  // QS[e=64][l=132]
#define OFF_K  (64*132)           // KS[e=64][j=132]
#define OFF_P  (2*64*132)         // PS[j=32][l=132]  (32-col chunk of P)
#define OFF_V  (OFF_P + 32*132)   // VS[s=32][e=64]
#define OFF_SR (OFF_V + 32*64)    // srow[128]
#define SMEM_FLOATS (OFF_SR + 128)
#define SMEM_BYTES  (SMEM_FLOATS * 4)   // 93184 B

typedef unsigned long long ull;

// ---------------------------------------------------------------------------
// Packed fp32x2 helpers (sm_100+).
// ---------------------------------------------------------------------------
__device__ __forceinline__ void fma2(ull& d, ull a, ull b) {
    asm("fma.rn.f32x2 %0, %1, %2, %0;" : "+l"(d) : "l"(a), "l"(b));
}
__device__ __forceinline__ ull pack2(float x, float y) {
    ull r;
    asm("mov.b64 %0, {%1, %2};" : "=l"(r) : "f"(x), "f"(y));
    return r;
}
__device__ __forceinline__ float2 unpack2(ull v) {
    float2 f;
    asm("mov.b64 {%0, %1}, %2;" : "=f"(f.x), "=f"(f.y) : "l"(v));
    return f;
}

// ---------------------------------------------------------------------------
// K0: per-row sigma transform (pow in double, rounded to f32, then -1 in f32
// to match the reference's fp32 quantization of the cancellation).
// ---------------------------------------------------------------------------
__global__ void k_sig(const float* __restrict__ sigma) {
    int i = blockIdx.x * 256 + threadIdx.x;
    if (i >= NROWS) return;
    int bh = i >> 11;
    int l  = i & 2047;
    int b = bh >> 3, h = bh & 7;
    float x = sigma[((size_t)b * LL + l) * HH + h];
    float s32 = (float)(1.0 / (1.0 + exp(-5.0 * (double)x)));
    float sg  = s32 + 1e-5f;
    float p   = (float)exp((double)sg * 1.0986122886681098);  // 3^sg, f32-rounded
    float s   = p - 1.0f;
    g_sigv[i]   = s;
    g_coef[i]   = 1.0f / (2.5066282746310002f * s);
    g_inv2s2[i] = 1.0f / (2.0f * s * s);
}

// ---------------------------------------------------------------------------
// Fused flash-style kernel: per (bh, 128-row block)
//   loop tj: S = Q·K^T tile -> exp -> {gmem series (unnormalized), smem P chunk}
//            O += P·V  (4 chunks of 32 columns)
//   then: rowsum reduce -> write O (normalized) -> renormalize own series rows.
// Microtile: rows ty*8+r (blocked), cols tx+16c (cyclic -> conflict-free PS
// stores and coalesced series stores). fp32x2-packed row pairs.
// ---------------------------------------------------------------------------
__global__ void __launch_bounds__(256) k_fused(const float* __restrict__ Q,
                                               const float* __restrict__ K,
                                               const float* __restrict__ V,
                                               float* __restrict__ series,
                                               float* __restrict__ out) {
    extern __shared__ float sm[];
    int bh = blockIdx.y, b = bh >> 3, h = bh & 7;
    int ti = 15 - blockIdx.x;          // heavy row-blocks first
    int l0 = ti * 128;
    int tid = threadIdx.x, tx = tid & 15, ty = tid >> 4;

    const float* Qb = Q + (size_t)b * LL * STRIDE_L + h * EE;
    const float* Kb = K + (size_t)b * LL * STRIDE_L + h * EE;
    const float* Vb = V + (size_t)b * LL * STRIDE_L + h * EE;
    float* Srow = series + ((size_t)bh * LL + l0) * LL;

    if (tid < 128) sm[OFF_SR + tid] = 0.f;

    // Load Q tile once: QS[e][l], gmem-coalesced (64 consecutive e per row)
    {
        int e = tid & 63, lr = tid >> 6;
#pragma unroll
        for (int it = 0; it < 32; it++) {
            int l = lr + it * 4;
            sm[OFF_Q + e * 132 + l] = Qb[(size_t)(l0 + l) * STRIDE_L + e];
        }
    }

    float lsum[8];
#pragma unroll
    for (int r = 0; r < 8; r++) lsum[r] = 0.f;

    ull acc_o[4][4];                   // O accumulator [row-pair][e-col]
#pragma unroll
    for (int r2 = 0; r2 < 4; r2++)
#pragma unroll
        for (int c = 0; c < 4; c++) acc_o[r2][c] = 0ull;

    for (int tj = 0; tj <= ti; tj++) {
        int j0 = tj * 128;
        // Load K tile: KS[e][j]
        {
            int e = tid & 63, lr = tid >> 6;
#pragma unroll
            for (int it = 0; it < 32; it++) {
                int l = lr + it * 4;
                sm[OFF_K + e * 132 + l] = Kb[(size_t)(j0 + l) * STRIDE_L + e];
            }
        }
        __syncthreads();

        // GEMM1: acc2[row-pair][c], cols j = tx + 16c
        ull acc2[4][8];
#pragma unroll
        for (int r2 = 0; r2 < 4; r2++)
#pragma unroll
            for (int c = 0; c < 8; c++) acc2[r2][c] = 0ull;

#pragma unroll 4
        for (int kk = 0; kk < 64; kk++) {
            ulonglong2 qa = *(const ulonglong2*)&sm[OFF_Q + kk * 132 + ty * 8];
            ulonglong2 qb = *(const ulonglong2*)&sm[OFF_Q + kk * 132 + ty * 8 + 4];
            ull a2[4] = {qa.x, qa.y, qb.x, qb.y};
#pragma unroll
            for (int c = 0; c < 8; c++) {
                float bv = sm[OFF_K + kk * 132 + tx + 16 * c];
                ull bb = pack2(bv, bv);
#pragma unroll
                for (int r2 = 0; r2 < 4; r2++) fma2(acc2[r2][c], a2[r2], bb);
            }
        }

        // Epilogue + PV in 4 chunks of 32 columns
        for (int sc = 0; sc < 4; sc++) {
            __syncthreads();   // previous chunk's GEMM2 done with PS/VS
#pragma unroll
            for (int cc = 0; cc < 2; cc++) {
                int c  = sc * 2 + cc;
                int gj = j0 + tx + 16 * c;
                int jl = tx + 16 * cc;           // local col in PS chunk
                float pcol[8];
#pragma unroll
                for (int r2 = 0; r2 < 4; r2++) {
                    float2 v = unpack2(acc2[r2][c]);
                    int lr0 = ty * 8 + 2 * r2;
                    int gl0 = l0 + lr0;
                    float e0 = __expf(SCALEF * v.x);
                    float e1 = __expf(SCALEF * v.y);
                    e0 = (gj <= gl0)     ? e0 : 0.f;
                    e1 = (gj <= gl0 + 1) ? e1 : 0.f;
                    lsum[2 * r2]     += e0;
                    lsum[2 * r2 + 1] += e1;
                    pcol[2 * r2]     = e0;
                    pcol[2 * r2 + 1] = e1;
                    Srow[(size_t)lr0 * LL + gj]       = e0;   // unnormalized
                    Srow[(size_t)(lr0 + 1) * LL + gj] = e1;
                }
                // PS[jl][l] — banks tx*4 mod 32: conflict-free float4
                *(float4*)&sm[OFF_P + jl * 132 + ty * 8] =
                    make_float4(pcol[0], pcol[1], pcol[2], pcol[3]);
                *(float4*)&sm[OFF_P + jl * 132 + ty * 8 + 4] =
                    make_float4(pcol[4], pcol[5], pcol[6], pcol[7]);
            }
            // Load VS chunk: s in [j0+sc*32, +32)
            {
                int e = tid & 63, sr = tid >> 6;
#pragma unroll
                for (int it = 0; it < 8; it++) {
                    int s = sr + it * 4;
                    sm[OFF_V + s * 64 + e] =
                        Vb[(size_t)(j0 + sc * 32 + s) * STRIDE_L + e];
                }
            }
            __syncthreads();
            // GEMM2: O += P_chunk @ V_chunk
#pragma unroll 4
            for (int ss = 0; ss < 32; ss++) {
                ulonglong2 pa = *(const ulonglong2*)&sm[OFF_P + ss * 132 + ty * 8];
                ulonglong2 pb = *(const ulonglong2*)&sm[OFF_P + ss * 132 + ty * 8 + 4];
                ull a2[4] = {pa.x, pa.y, pb.x, pb.y};
                float4 bv = *(const float4*)&sm[OFF_V + ss * 64 + tx * 4];
                float bf[4] = {bv.x, bv.y, bv.z, bv.w};
#pragma unroll
                for (int c4 = 0; c4 < 4; c4++) {
                    ull bb = pack2(bf[c4], bf[c4]);
#pragma unroll
                    for (int r2 = 0; r2 < 4; r2++) fma2(acc_o[r2][c4], a2[r2], bb);
                }
            }
        }
    }

    // Row-sum reduction (16 tx duplicates per row -> smem atomics)
#pragma unroll
    for (int r = 0; r < 8; r++) atomicAdd(&sm[OFF_SR + ty * 8 + r], lsum[r]);
    __syncthreads();

    // Write O, normalized
#pragma unroll
    for (int r2 = 0; r2 < 4; r2++) {
        int lr0 = ty * 8 + 2 * r2;
        int gl0 = l0 + lr0, gl1 = gl0 + 1;
        float i0 = 1.0f / sm[OFF_SR + lr0];
        float i1 = 1.0f / sm[OFF_SR + lr0 + 1];
        float p0[4], p1[4];
#pragma unroll
        for (int c4 = 0; c4 < 4; c4++) {
            float2 v = unpack2(acc_o[r2][c4]);
            p0[c4] = v.x * i0;
            p1[c4] = v.y * i1;
        }
        float* d0 = out + ((size_t)(b * LL + gl0) * HH + h) * EE + tx * 4;
        float* d1 = out + ((size_t)(b * LL + gl1) * HH + h) * EE + tx * 4;
        *(float4*)d0 = make_float4(p0[0], p0[1], p0[2], p0[3]);
        *(float4*)d1 = make_float4(p1[0], p1[1], p1[2], p1[3]);
    }

    // Renormalize this CTA's series rows in place (writes are L2-hot).
    // __syncthreads above ordered all series stores before these loads.
    {
        int w = tid >> 5, lane = tid & 31;
        int ncols4 = (l0 + 128) >> 2;
        for (int rr = w; rr < 128; rr += 8) {
            float inv = 1.0f / sm[OFF_SR + rr];
            float* rowp = series + ((size_t)bh * LL + l0 + rr) * LL;
            for (int c4i = lane; c4i < ncols4; c4i += 32) {
                float4 s = *(float4*)&rowp[c4i * 4];
                s.x *= inv; s.y *= inv; s.z *= inv; s.w *= inv;
                *(float4*)&rowp[c4i * 4] = s;
            }
        }
    }
}

// ---------------------------------------------------------------------------
// k_prior: prior + sig everywhere; zero series ONLY in strictly-upper tiles.
// ---------------------------------------------------------------------------
__global__ void __launch_bounds__(256) k_prior(float* __restrict__ prior,
                                               float* __restrict__ sig,
                                               float* __restrict__ series) {
    int bh = blockIdx.z;
    int ti = blockIdx.y, tj = blockIdx.x;
    int l0 = ti * 128, j0 = tj * 128;
    bool upper = (tj > ti);
    int tid = threadIdx.x;
    int c4 = (tid & 31) * 4;
    int r0 = tid >> 5;
#pragma unroll 4
    for (int it = 0; it < 16; it++) {
        int lr = r0 + it * 8;
        int gl = l0 + lr;
        size_t rowi = (size_t)bh * LL + gl;
        float coef = g_coef[rowi];
        float i2s  = g_inv2s2[rowi];
        float sv   = g_sigv[rowi];
        float p[4];
#pragma unroll
        for (int c = 0; c < 4; c++) {
            int gj = j0 + c4 + c;
            int d  = gl - gj;
            float d2 = (float)(d * d);
            p[c] = coef * __expf(-d2 * i2s);
        }
        size_t idx = rowi * LL + j0 + c4;
        *(float4*)&prior[idx] = make_float4(p[0], p[1], p[2], p[3]);
        *(float4*)&sig[idx]   = make_float4(sv, sv, sv, sv);
        if (upper)
            *(float4*)&series[idx] = make_float4(0.f, 0.f, 0.f, 0.f);
    }
}

// ---------------------------------------------------------------------------
extern "C" void kernel_launch(void* const* d_in, const int* in_sizes, int n_in,
                              void* d_out, int out_size) {
    const float* Q = (const float*)d_in[0];
    const float* K = (const float*)d_in[1];
    const float* V = (const float*)d_in[2];
    const float* S = (const float*)d_in[3];
    float* out = (float*)d_out;

    float* outV      = out;                                   // [B,L,H,E]
    float* outSeries = outV + (size_t)BB * LL * HH * EE;      // [B,H,L,L]
    float* outPrior  = outSeries + (size_t)NBH * LL * LL;     // [B,H,L,L]
    float* outSig    = outPrior + (size_t)NBH * LL * LL;      // [B,H,L,L]

    // Opt-in to >48KB dynamic smem (attribute set; not a stream operation).
    cudaFuncSetAttribute(k_fused, cudaFuncAttributeMaxDynamicSharedMemorySize,
                         SMEM_BYTES);

    k_sig<<<NROWS / 256, 256>>>(S);
    k_fused<<<dim3(16, NBH), 256, SMEM_BYTES>>>(Q, K, V, outSeries, outV);
    k_prior<<<dim3(16, 16, NBH), 256>>>(outPrior, outSig, outSeries);
}

// round 6
// speedup vs baseline: 2.3691x; 1.7797x over previous
#include <cuda_runtime.h>
#include <cuda_bf16.h>
#include <cstdint>
#include <math.h>

// Problem constants (B=4, L=2048, H=8, E=64)
#define BB 4
#define LL 2048
#define HH 8
#define EE 64
#define NBH (BB*HH)           // 32
#define NROWS (NBH*LL)        // 65536
#define SCALEF 0.125f
#define STRIDE_L (HH*EE)      // 512

// Scratch (device globals)
__device__ float g_sigv[NROWS];
__device__ float g_coef[NROWS];
__device__ float g_inv2s2[NROWS];

// ---- smem layout (bytes). bf16 tiles: 128 rows x 64 cols = 16384 B, SW128 ----
#define OFF_INV   0            // 128 f32 rowsum reciprocals
#define OFF_QHI   1024
#define OFF_QLO   17408
#define OFF_KHI   33792
#define OFF_KLO   50176
#define OFF_VHI   66560
#define OFF_VLO   82944
#define SMEM_BYTES 99840

__device__ __forceinline__ uint32_t swz(uint32_t x) { return x ^ ((x >> 3) & 0x70); }

__device__ __forceinline__ uint32_t smem_u32(const void* p) {
    uint32_t a;
    asm("{ .reg .u64 t; cvta.to.shared.u64 t, %1; cvt.u32.u64 %0, t; }"
        : "=r"(a) : "l"(p));
    return a;
}
__device__ __forceinline__ void ldsm4(uint32_t r[4], uint32_t addr) {
    asm volatile("ldmatrix.sync.aligned.m8n8.x4.shared.b16 {%0,%1,%2,%3}, [%4];"
                 : "=r"(r[0]), "=r"(r[1]), "=r"(r[2]), "=r"(r[3]) : "r"(addr));
}
__device__ __forceinline__ void ldsm4t(uint32_t r[4], uint32_t addr) {
    asm volatile("ldmatrix.sync.aligned.m8n8.x4.trans.shared.b16 {%0,%1,%2,%3}, [%4];"
                 : "=r"(r[0]), "=r"(r[1]), "=r"(r[2]), "=r"(r[3]) : "r"(addr));
}
__device__ __forceinline__ void mma_bf16(float d[4], const uint32_t a[4],
                                         uint32_t b0, uint32_t b1) {
    asm volatile(
        "mma.sync.aligned.m16n8k16.row.col.f32.bf16.bf16.f32 "
        "{%0,%1,%2,%3}, {%4,%5,%6,%7}, {%8,%9}, {%0,%1,%2,%3};"
        : "+f"(d[0]), "+f"(d[1]), "+f"(d[2]), "+f"(d[3])
        : "r"(a[0]), "r"(a[1]), "r"(a[2]), "r"(a[3]), "r"(b0), "r"(b1));
}
__device__ __forceinline__ uint32_t packbf(float a, float b) {   // a -> low half
    __nv_bfloat162 t = __float22bfloat162_rn(make_float2(a, b));
    return *reinterpret_cast<uint32_t*>(&t);
}
__device__ __forceinline__ uint32_t packresid(float a, float b, uint32_t hi) {
    __nv_bfloat162 t = *reinterpret_cast<__nv_bfloat162*>(&hi);
    return packbf(a - __bfloat162float(t.x), b - __bfloat162float(t.y));
}

// ---------------------------------------------------------------------------
// K0: per-row sigma transform (verified in R1-R3)
// ---------------------------------------------------------------------------
__global__ void k_sig(const float* __restrict__ sigma) {
    int i = blockIdx.x * 256 + threadIdx.x;
    if (i >= NROWS) return;
    int bh = i >> 11;
    int l  = i & 2047;
    int b = bh >> 3, h = bh & 7;
    float x = sigma[((size_t)b * LL + l) * HH + h];
    float s32 = (float)(1.0 / (1.0 + exp(-5.0 * (double)x)));
    float sg  = s32 + 1e-5f;
    float p   = (float)exp((double)sg * 1.0986122886681098);
    float s   = p - 1.0f;
    g_sigv[i]   = s;
    g_coef[i]   = 1.0f / (2.5066282746310002f * s);
    g_inv2s2[i] = 1.0f / (2.0f * s * s);
}

// ---------------------------------------------------------------------------
// Fused flash kernel, mma.sync bf16 hi/lo split. 256 threads, 8 warps,
// warp w owns output rows [w*16, w*16+16).
// ---------------------------------------------------------------------------
__global__ void __launch_bounds__(256, 1)
k_fused(const float* __restrict__ Q, const float* __restrict__ K,
        const float* __restrict__ V, float* __restrict__ series,
        float* __restrict__ out) {
    extern __shared__ __align__(1024) char smem[];
    float* smf = (float*)smem;
    uint32_t sb = smem_u32(smem);
    int tid = threadIdx.x, wid = tid >> 5, lane = tid & 31;
    int bh = blockIdx.y, b = bh >> 3, h = bh & 7;
    int ti = 15 - blockIdx.x, l0 = ti * 128;
    int R0 = wid * 16;
    int g = lane >> 2, tig = lane & 3;
    int L8 = lane & 7, m = lane >> 3;

    const float* Qb = Q + (size_t)b * LL * STRIDE_L + h * EE;
    const float* Kb = K + (size_t)b * LL * STRIDE_L + h * EE;
    const float* Vb = V + (size_t)b * LL * STRIDE_L + h * EE;
    float* Srow = series + ((size_t)bh * LL + l0) * LL;

    // ---- Q tile -> smem bf16 hi/lo, [l][e], SW128 rows of 128B ----
    {
        int e4 = tid & 15, r0 = tid >> 4;
#pragma unroll
        for (int ps = 0; ps < 8; ps++) {
            int row = r0 + ps * 16;
            float4 v = *(const float4*)&Qb[(size_t)(l0 + row) * STRIDE_L + e4 * 4];
            uint32_t h0 = packbf(v.x, v.y), h1 = packbf(v.z, v.w);
            uint32_t sw = swz(row * 128 + e4 * 8);
            *(uint2*)(smem + OFF_QHI + sw) = make_uint2(h0, h1);
            *(uint2*)(smem + OFF_QLO + sw) =
                make_uint2(packresid(v.x, v.y, h0), packresid(v.z, v.w, h1));
        }
    }
    __syncthreads();

    // ---- Preload Q fragments (4 k-steps, hi+lo) ----
    uint32_t qh[4][4], ql[4][4];
    {
        uint32_t ro = (uint32_t)(R0 + (m & 1) * 8 + L8) * 128 + (m >> 1) * 16;
#pragma unroll
        for (int ks = 0; ks < 4; ks++) {
            uint32_t sw = swz(ro + ks * 32);
            ldsm4(qh[ks], sb + OFF_QHI + sw);
            ldsm4(ql[ks], sb + OFF_QLO + sw);
        }
    }

    float oacc[8][4];
#pragma unroll
    for (int t = 0; t < 8; t++)
#pragma unroll
        for (int c = 0; c < 4; c++) oacc[t][c] = 0.f;
    float rs0 = 0.f, rs1 = 0.f;
    int gl0 = l0 + R0 + g, gl1 = gl0 + 8;

    // lane-offsets for B-fragment ldmatrix addresses
    uint32_t k_ro = (uint32_t)((m >> 1) * 8 + L8) * 128 + (m & 1) * 16;   // K (no trans)
    uint32_t v_ro = (uint32_t)((m & 1) * 8 + L8) * 128 + (m >> 1) * 16;   // V (trans)

    for (int tj = 0; tj <= ti; tj++) {
        int j0 = tj * 128;
        __syncthreads();   // previous tile's V reads complete
        // ---- K tile [j][e] hi/lo ----
        {
            int e4 = tid & 15, r0 = tid >> 4;
#pragma unroll
            for (int ps = 0; ps < 8; ps++) {
                int row = r0 + ps * 16;
                float4 v = *(const float4*)&Kb[(size_t)(j0 + row) * STRIDE_L + e4 * 4];
                uint32_t h0 = packbf(v.x, v.y), h1 = packbf(v.z, v.w);
                uint32_t sw = swz(row * 128 + e4 * 8);
                *(uint2*)(smem + OFF_KHI + sw) = make_uint2(h0, h1);
                *(uint2*)(smem + OFF_KLO + sw) =
                    make_uint2(packresid(v.x, v.y, h0), packresid(v.z, v.w, h1));
            }
        }
        // ---- V tile [s][e] hi/lo ----
        {
            int e4 = tid & 15, r0 = tid >> 4;
#pragma unroll
            for (int ps = 0; ps < 8; ps++) {
                int row = r0 + ps * 16;
                float4 v = *(const float4*)&Vb[(size_t)(j0 + row) * STRIDE_L + e4 * 4];
                uint32_t h0 = packbf(v.x, v.y), h1 = packbf(v.z, v.w);
                uint32_t sw = swz(row * 128 + e4 * 8);
                *(uint2*)(smem + OFF_VHI + sw) = make_uint2(h0, h1);
                *(uint2*)(smem + OFF_VLO + sw) =
                    make_uint2(packresid(v.x, v.y, h0), packresid(v.z, v.w, h1));
            }
        }
        __syncthreads();

        // ---- GEMM1: S = Q.K^T via 3-term bf16 split ----
        float sacc[16][4];
#pragma unroll
        for (int t = 0; t < 16; t++)
#pragma unroll
            for (int c = 0; c < 4; c++) sacc[t][c] = 0.f;

#pragma unroll
        for (int jp = 0; jp < 8; jp++) {
#pragma unroll
            for (int ks = 0; ks < 4; ks++) {
                uint32_t sw = swz(k_ro + (uint32_t)jp * 16 * 128 + ks * 32);
                uint32_t bh_[4], bl_[4];
                ldsm4(bh_, sb + OFF_KHI + sw);
                ldsm4(bl_, sb + OFF_KLO + sw);
                mma_bf16(sacc[2 * jp],     qh[ks], bh_[0], bh_[1]);
                mma_bf16(sacc[2 * jp],     qh[ks], bl_[0], bl_[1]);
                mma_bf16(sacc[2 * jp],     ql[ks], bh_[0], bh_[1]);
                mma_bf16(sacc[2 * jp + 1], qh[ks], bh_[2], bh_[3]);
                mma_bf16(sacc[2 * jp + 1], qh[ks], bl_[2], bl_[3]);
                mma_bf16(sacc[2 * jp + 1], ql[ks], bh_[2], bh_[3]);
            }
        }

        // ---- softmax numerator + series store (unnormalized) ----
#pragma unroll
        for (int t = 0; t < 16; t++) {
            int gj = j0 + t * 8 + tig * 2;
            float e0 = __expf(SCALEF * sacc[t][0]);
            float e1 = __expf(SCALEF * sacc[t][1]);
            float e2 = __expf(SCALEF * sacc[t][2]);
            float e3 = __expf(SCALEF * sacc[t][3]);
            e0 = (gj     <= gl0) ? e0 : 0.f;
            e1 = (gj + 1 <= gl0) ? e1 : 0.f;
            e2 = (gj     <= gl1) ? e2 : 0.f;
            e3 = (gj + 1 <= gl1) ? e3 : 0.f;
            rs0 += e0 + e1;
            rs1 += e2 + e3;
            sacc[t][0] = e0; sacc[t][1] = e1; sacc[t][2] = e2; sacc[t][3] = e3;
            *(float2*)&Srow[(size_t)(R0 + g) * LL + gj]     = make_float2(e0, e1);
            *(float2*)&Srow[(size_t)(R0 + 8 + g) * LL + gj] = make_float2(e2, e3);
        }

        // ---- GEMM2: O += P.V, P fragments straight from registers ----
#pragma unroll
        for (int kk = 0; kk < 8; kk++) {
            const float* x = sacc[2 * kk];
            const float* y = sacc[2 * kk + 1];
            uint32_t ah[4], al[4];
            ah[0] = packbf(x[0], x[1]); ah[1] = packbf(x[2], x[3]);
            ah[2] = packbf(y[0], y[1]); ah[3] = packbf(y[2], y[3]);
            al[0] = packresid(x[0], x[1], ah[0]);
            al[1] = packresid(x[2], x[3], ah[1]);
            al[2] = packresid(y[0], y[1], ah[2]);
            al[3] = packresid(y[2], y[3], ah[3]);
#pragma unroll
            for (int ep = 0; ep < 4; ep++) {
                uint32_t sw = swz(v_ro + (uint32_t)kk * 16 * 128 + ep * 32);
                uint32_t vh_[4], vl_[4];
                ldsm4t(vh_, sb + OFF_VHI + sw);
                ldsm4t(vl_, sb + OFF_VLO + sw);
                mma_bf16(oacc[2 * ep],     ah, vh_[0], vh_[1]);
                mma_bf16(oacc[2 * ep],     ah, vl_[0], vl_[1]);
                mma_bf16(oacc[2 * ep],     al, vh_[0], vh_[1]);
                mma_bf16(oacc[2 * ep + 1], ah, vh_[2], vh_[3]);
                mma_bf16(oacc[2 * ep + 1], ah, vl_[2], vl_[3]);
                mma_bf16(oacc[2 * ep + 1], al, vh_[2], vh_[3]);
            }
        }
    }

    // ---- row sums: reduce over the 4 tig lanes ----
    rs0 += __shfl_xor_sync(0xFFFFFFFF, rs0, 1);
    rs0 += __shfl_xor_sync(0xFFFFFFFF, rs0, 2);
    rs1 += __shfl_xor_sync(0xFFFFFFFF, rs1, 1);
    rs1 += __shfl_xor_sync(0xFFFFFFFF, rs1, 2);
    float inv0 = 1.0f / rs0, inv1 = 1.0f / rs1;
    if (tig == 0) {
        smf[OFF_INV / 4 + R0 + g]     = inv0;
        smf[OFF_INV / 4 + R0 + 8 + g] = inv1;
    }

    // ---- O epilogue (own rows; no cross-warp data needed) ----
#pragma unroll
    for (int t = 0; t < 8; t++) {
        int col = t * 8 + tig * 2;
        float* d0 = out + (((size_t)b * LL + gl0) * HH + h) * EE + col;
        float* d1 = out + (((size_t)b * LL + gl1) * HH + h) * EE + col;
        *(float2*)d0 = make_float2(oacc[t][0] * inv0, oacc[t][1] * inv0);
        *(float2*)d1 = make_float2(oacc[t][2] * inv1, oacc[t][3] * inv1);
    }
    __syncthreads();

    // ---- in-place series renormalization (rows of this CTA's block) ----
    {
        int ncols4 = (l0 + 128) >> 2;
        for (int rr = wid; rr < 128; rr += 8) {
            float inv = smf[OFF_INV / 4 + rr];
            float* rowp = series + ((size_t)bh * LL + l0 + rr) * LL;
            for (int c4 = lane; c4 < ncols4; c4 += 32) {
                float4 s = *(float4*)&rowp[c4 * 4];
                s.x *= inv; s.y *= inv; s.z *= inv; s.w *= inv;
                *(float4*)&rowp[c4 * 4] = s;
            }
        }
    }
}

// ---------------------------------------------------------------------------
// k_prior: prior + sig everywhere; zero series in strictly-upper tiles.
// ---------------------------------------------------------------------------
__global__ void __launch_bounds__(256) k_prior(float* __restrict__ prior,
                                               float* __restrict__ sig,
                                               float* __restrict__ series) {
    int bh = blockIdx.z;
    int ti = blockIdx.y, tj = blockIdx.x;
    int l0 = ti * 128, j0 = tj * 128;
    bool upper = (tj > ti);
    int tid = threadIdx.x;
    int c4 = (tid & 31) * 4;
    int r0 = tid >> 5;
#pragma unroll 4
    for (int it = 0; it < 16; it++) {
        int lr = r0 + it * 8;
        int gl = l0 + lr;
        size_t rowi = (size_t)bh * LL + gl;
        float coef = g_coef[rowi];
        float i2s  = g_inv2s2[rowi];
        float sv   = g_sigv[rowi];
        float p[4];
#pragma unroll
        for (int c = 0; c < 4; c++) {
            int gj = j0 + c4 + c;
            int d  = gl - gj;
            float d2 = (float)(d * d);
            p[c] = coef * __expf(-d2 * i2s);
        }
        size_t idx = rowi * LL + j0 + c4;
        *(float4*)&prior[idx] = make_float4(p[0], p[1], p[2], p[3]);
        *(float4*)&sig[idx]   = make_float4(sv, sv, sv, sv);
        if (upper)
            *(float4*)&series[idx] = make_float4(0.f, 0.f, 0.f, 0.f);
    }
}

// ---------------------------------------------------------------------------
extern "C" void kernel_launch(void* const* d_in, const int* in_sizes, int n_in,
                              void* d_out, int out_size) {
    const float* Q = (const float*)d_in[0];
    const float* K = (const float*)d_in[1];
    const float* V = (const float*)d_in[2];
    const float* S = (const float*)d_in[3];
    float* out = (float*)d_out;

    float* outV      = out;
    float* outSeries = outV + (size_t)BB * LL * HH * EE;
    float* outPrior  = outSeries + (size_t)NBH * LL * LL;
    float* outSig    = outPrior + (size_t)NBH * LL * LL;

    cudaFuncSetAttribute(k_fused, cudaFuncAttributeMaxDynamicSharedMemorySize,
                         SMEM_BYTES);

    k_sig<<<NROWS / 256, 256>>>(S);
    k_fused<<<dim3(16, NBH), 256, SMEM_BYTES>>>(Q, K, V, outSeries, outV);
    k_prior<<<dim3(16, 16, NBH), 256>>>(outPrior, outSig, outSeries);
}